// round 5
// baseline (speedup 1.0000x reference)
#include <cuda_runtime.h>
#include <cuda_bf16.h>
#include <cuda_fp16.h>
#include <math_constants.h>

#define NROW 32768
#define CDIM 256
#define NE   1024
#define MARGIN 8e-3f
#define CAP  48

// ---- static device scratch (allocation-free rule) ----
__device__ float          g_zrm[(size_t)NROW * CDIM];   // z row-major [n][c] fp32
__device__ __nv_bfloat16  g_zbf[(size_t)NROW * CDIM];   // bf16(z) [n][c]
__device__ __nv_bfloat16  g_ebf[(size_t)NE * CDIM];     // bf16(emb) [j][k]
__device__ float          g_se[NE];
__device__ double         g_partial[256];

// ================= PTX helpers (baseline sm_80 ISA only) =================
__device__ __forceinline__ unsigned smem_u32(const void* p) {
    unsigned a;
    asm("{ .reg .u64 t; cvta.to.shared.u64 t, %1; cvt.u32.u64 %0, t; }" : "=r"(a) : "l"(p));
    return a;
}
__device__ __forceinline__ void cp16(unsigned dst, const void* src) {
    asm volatile("cp.async.cg.shared.global [%0], [%1], 16;" :: "r"(dst), "l"(src));
}
#define CP_COMMIT() asm volatile("cp.async.commit_group;" ::: "memory")
#define CP_WAIT(n)  asm volatile("cp.async.wait_group %0;" :: "n"(n) : "memory")

__device__ __forceinline__ void ldsm4(unsigned& r0, unsigned& r1, unsigned& r2, unsigned& r3,
                                      unsigned addr) {
    asm volatile("ldmatrix.sync.aligned.m8n8.x4.shared.b16 {%0,%1,%2,%3}, [%4];"
        : "=r"(r0), "=r"(r1), "=r"(r2), "=r"(r3) : "r"(addr));
}
__device__ __forceinline__ void mma16816(float* c, const unsigned* a, unsigned b0, unsigned b1) {
    asm volatile("mma.sync.aligned.m16n8k16.row.col.f32.bf16.bf16.f32 "
        "{%0,%1,%2,%3}, {%4,%5,%6,%7}, {%8,%9}, {%0,%1,%2,%3};"
        : "+f"(c[0]), "+f"(c[1]), "+f"(c[2]), "+f"(c[3])
        : "r"(a[0]), "r"(a[1]), "r"(a[2]), "r"(a[3]), "r"(b0), "r"(b1));
}
// monotonic float<->uint map (for atomicMin-based running row minimum)
__device__ __forceinline__ unsigned fmapu(float f) {
    unsigned b = __float_as_uint(f);
    return (b & 0x80000000u) ? ~b : (b | 0x80000000u);
}
__device__ __forceinline__ float funmapu(unsigned u) {
    return (u & 0x80000000u) ? __uint_as_float(u & 0x7fffffffu) : __uint_as_float(~u);
}

// ================= prep kernels =================
__global__ void zprep_kernel(const float* __restrict__ z) {
    __shared__ float tile[32][33];
    int tx = threadIdx.x, ty = threadIdx.y;
    int hw0 = blockIdx.x * 32, c0 = blockIdx.y * 32, b = blockIdx.z;
    #pragma unroll
    for (int yy = 0; yy < 4; yy++) {
        int cl = ty + yy * 8;
        tile[cl][tx] = z[((size_t)(b * 256 + c0 + cl)) * 1024 + hw0 + tx];
    }
    __syncthreads();
    #pragma unroll
    for (int yy = 0; yy < 4; yy++) {
        int rl = ty + yy * 8;
        size_t n = (size_t)b * 1024 + hw0 + rl;
        float v = tile[tx][rl];
        g_zrm[n * 256 + c0 + tx] = v;
        g_zbf[n * 256 + c0 + tx] = __float2bfloat16(v);
    }
}

__global__ void eprep_kernel(const float* __restrict__ e) {
    int i = blockIdx.x * 256 + threadIdx.x;
    g_ebf[i] = __float2bfloat16(e[i]);
}

// per-code norms (verbatim R1 rounding — known-passing)
__global__ void se_kernel(const float* __restrict__ e) {
    int j = blockIdx.x;
    float4 v = *(const float4*)&e[j * 256 + threadIdx.x * 4];
    float s = __fadd_rn(__fadd_rn(__fmul_rn(v.x,v.x), __fmul_rn(v.y,v.y)),
                        __fadd_rn(__fmul_rn(v.z,v.z), __fmul_rn(v.w,v.w)));
    for (int off = 16; off; off >>= 1) s += __shfl_down_sync(0xffffffffu, s, off);
    __shared__ float r2[2];
    if ((threadIdx.x & 31) == 0) r2[threadIdx.x >> 5] = s;
    __syncthreads();
    if (threadIdx.x == 0) g_se[j] = __fadd_rn(r2[0], r2[1]);
}

// ================= fused HMMA scoring + online shortlist + exact rescore =================
// smem: se 4KB | A 64KB | B 2x64KB | min 512B | cnt 512B | sz 512B | ws 256B | lists 12KB
#define SE_OFF   0
#define A_OFF    4096
#define B_OFF    (4096 + 65536)
#define MIN_OFF  (B_OFF + 131072)          // 200704
#define CNT_OFF  (MIN_OFF + 512)
#define SZ_OFF   (CNT_OFF + 512)
#define WS_OFF   (SZ_OFF + 512)
#define LIST_OFF (WS_OFF + 256)
#define SMEM_T   (LIST_OFF + 128 * CAP * 2)  // 214784

__global__ void __launch_bounds__(512, 1) gemm_kernel(const float* __restrict__ emb,
                                                      float* __restrict__ out) {
    extern __shared__ char sm[];
    unsigned smb = smem_u32(sm);
    const int tid = threadIdx.x, l = tid & 31, w = tid >> 5;
    const int wm = w & 3, wn = w >> 2;           // 4x4 warp grid, 32x32 tiles
    const int row0 = blockIdx.x * 128;
    float* se_sm = (float*)(sm + SE_OFF);
    unsigned* sm_min = (unsigned*)(sm + MIN_OFF);
    int* sm_cnt = (int*)(sm + CNT_OFF);
    float* sz_sm = (float*)(sm + SZ_OFF);
    double* ws = (double*)(sm + WS_OFF);
    unsigned short* sm_list = (unsigned short*)(sm + LIST_OFF);

    if (tid < 256) ((float4*)se_sm)[tid] = ((const float4*)g_se)[tid];
    if (tid < 128) { sm_min[tid] = 0xFFFFFFFFu; sm_cnt[tid] = 0; }

    // ---- group 0: A tile + B chunk 0 ----
    const char* zsrc = (const char*)g_zbf + (size_t)row0 * 512;
    #pragma unroll
    for (int i = 0; i < 8; i++) {
        int f = tid + i * 512, r = f >> 5, kb16 = f & 31;
        cp16(smb + A_OFF + r * 512 + ((kb16 * 16) ^ ((r & 7) << 4)),
             zsrc + (size_t)r * 512 + kb16 * 16);
    }
    const char* esrc = (const char*)g_ebf;
    #pragma unroll
    for (int i = 0; i < 8; i++) {
        int f = tid + i * 512, r = f >> 5, kb16 = f & 31;
        cp16(smb + B_OFF + r * 512 + ((kb16 * 16) ^ ((r & 7) << 4)),
             esrc + (size_t)r * 512 + kb16 * 16);
    }
    CP_COMMIT();

    const unsigned c16 = ((l >> 4) & 1) * 16;
    unsigned aBase[2], xA[2];
    #pragma unroll
    for (int mf = 0; mf < 2; mf++) {
        int r = wm * 32 + mf * 16 + (l & 15);
        aBase[mf] = smb + A_OFF + r * 512;
        xA[mf] = c16 ^ ((r & 7) << 4);
    }
    unsigned bRow[2], xB[2];
    #pragma unroll
    for (int nfp = 0; nfp < 2; nfp++) {
        int r = wn * 32 + nfp * 16 + ((l >> 3) & 1) * 8 + (l & 7);
        bRow[nfp] = r * 512;
        xB[nfp] = c16 ^ ((r & 7) << 4);
    }

    for (int t = 0; t < 8; t++) {
        if (t < 7) {
            const char* src = esrc + (size_t)(t + 1) * 128 * 512;
            unsigned dstb = smb + B_OFF + ((t + 1) & 1) * 65536;
            #pragma unroll
            for (int i = 0; i < 8; i++) {
                int f = tid + i * 512, r = f >> 5, kb16 = f & 31;
                cp16(dstb + r * 512 + ((kb16 * 16) ^ ((r & 7) << 4)),
                     src + (size_t)r * 512 + kb16 * 16);
            }
            CP_COMMIT();
            CP_WAIT(1);
        } else {
            CP_WAIT(0);
        }
        __syncthreads();

        float acc[2][4][4];
        #pragma unroll
        for (int mf = 0; mf < 2; mf++)
            #pragma unroll
            for (int nf = 0; nf < 4; nf++)
                #pragma unroll
                for (int q = 0; q < 4; q++) acc[mf][nf][q] = 0.f;

        unsigned bB = smb + B_OFF + (t & 1) * 65536;
        #pragma unroll
        for (int ks = 0; ks < 16; ks++) {
            unsigned afr[2][4], bfr[8];
            #pragma unroll
            for (int mf = 0; mf < 2; mf++)
                ldsm4(afr[mf][0], afr[mf][1], afr[mf][2], afr[mf][3],
                      aBase[mf] + ((ks << 5) ^ xA[mf]));
            #pragma unroll
            for (int nfp = 0; nfp < 2; nfp++) {
                unsigned q0, q1, q2, q3;
                ldsm4(q0, q1, q2, q3, bB + bRow[nfp] + ((ks << 5) ^ xB[nfp]));
                bfr[nfp * 4 + 0] = q0; bfr[nfp * 4 + 1] = q2;
                bfr[nfp * 4 + 2] = q1; bfr[nfp * 4 + 3] = q3;
            }
            #pragma unroll
            for (int mf = 0; mf < 2; mf++)
                #pragma unroll
                for (int nf = 0; nf < 4; nf++)
                    mma16816(acc[mf][nf], afr[mf], bfr[nf * 2], bfr[nf * 2 + 1]);
        }

        // ---- online shortlist epilogue (no gmem score traffic) ----
        #pragma unroll
        for (int mf = 0; mf < 2; mf++) {
            int r0l = wm * 32 + mf * 16 + (l >> 2);
            int r1l = r0l + 8;
            // pass 1: chunk-local row min over this warp's 32 columns
            float mn0 = CUDART_INF_F, mn1 = CUDART_INF_F;
            #pragma unroll
            for (int nf = 0; nf < 4; nf++) {
                int gc = t * 128 + wn * 32 + nf * 8 + (l & 3) * 2;
                float se0 = se_sm[gc], se1 = se_sm[gc + 1];
                mn0 = fminf(mn0, fminf(fmaf(-2.f, acc[mf][nf][0], se0),
                                       fmaf(-2.f, acc[mf][nf][1], se1)));
                mn1 = fminf(mn1, fminf(fmaf(-2.f, acc[mf][nf][2], se0),
                                       fmaf(-2.f, acc[mf][nf][3], se1)));
            }
            mn0 = fminf(mn0, __shfl_xor_sync(0xffffffffu, mn0, 1));
            mn0 = fminf(mn0, __shfl_xor_sync(0xffffffffu, mn0, 2));
            mn1 = fminf(mn1, __shfl_xor_sync(0xffffffffu, mn1, 1));
            mn1 = fminf(mn1, __shfl_xor_sync(0xffffffffu, mn1, 2));
            if ((l & 3) == 0) {
                atomicMin(&sm_min[r0l], fmapu(mn0));
                atomicMin(&sm_min[r1l], fmapu(mn1));
            }
            __syncwarp();
            float thr0 = fminf(funmapu(((volatile unsigned*)sm_min)[r0l]), mn0) + MARGIN;
            float thr1 = fminf(funmapu(((volatile unsigned*)sm_min)[r1l]), mn1) + MARGIN;
            // pass 2: push candidates (superset of true candidates; exact rescore later)
            #pragma unroll
            for (int nf = 0; nf < 4; nf++) {
                int gc = t * 128 + wn * 32 + nf * 8 + (l & 3) * 2;
                float se0 = se_sm[gc], se1 = se_sm[gc + 1];
                float s00 = fmaf(-2.f, acc[mf][nf][0], se0);
                float s01 = fmaf(-2.f, acc[mf][nf][1], se1);
                float s10 = fmaf(-2.f, acc[mf][nf][2], se0);
                float s11 = fmaf(-2.f, acc[mf][nf][3], se1);
                if (s00 <= thr0) { int p = atomicAdd(&sm_cnt[r0l], 1); if (p < CAP) sm_list[r0l * CAP + p] = (unsigned short)gc; }
                if (s01 <= thr0) { int p = atomicAdd(&sm_cnt[r0l], 1); if (p < CAP) sm_list[r0l * CAP + p] = (unsigned short)(gc + 1); }
                if (s10 <= thr1) { int p = atomicAdd(&sm_cnt[r1l], 1); if (p < CAP) sm_list[r1l * CAP + p] = (unsigned short)gc; }
                if (s11 <= thr1) { int p = atomicAdd(&sm_cnt[r1l], 1); if (p < CAP) sm_list[r1l * CAP + p] = (unsigned short)(gc + 1); }
            }
        }
        __syncthreads();
    }

    // ---- tail: exact rescore (bit-identical to R1 arithmetic) ----
    // per-row sz, R1-exact: 8 strided partials (mul+add, not fma), ordered combine
    #pragma unroll
    for (int pass = 0; pass < 2; pass++) {
        int r = w * 8 + pass * 4 + (l >> 3);
        int y = l & 7;
        const float* zp = g_zrm + (size_t)(row0 + r) * CDIM;
        float p = 0.f;
        #pragma unroll 8
        for (int i = 0; i < 32; i++) {
            float v = zp[y + 8 * i];
            p = __fadd_rn(p, __fmul_rn(v, v));
        }
        int base = l & 24;
        float tt = __shfl_sync(0xffffffffu, p, base);
        #pragma unroll
        for (int yy = 1; yy < 8; yy++)
            tt = __fadd_rn(tt, __shfl_sync(0xffffffffu, p, base + yy));
        if (y == 0) sz_sm[r] = tt;
    }
    __syncwarp();

    double wsum = 0.0;
    for (int rr = 0; rr < 8; rr++) {
        int r = w * 8 + rr;
        int c0 = sm_cnt[r];
        bool ovf = (c0 > CAP);
        int n = ovf ? NE : c0;
        float szr = sz_sm[r];
        const float* zp = g_zrm + (size_t)(row0 + r) * CDIM;
        float bd = CUDART_INF_F; int bj = 0x7fffffff;
        for (int i = l; i < n; i += 32) {
            int j = ovf ? i : (int)sm_list[r * CAP + i];
            const float* ep = emb + (size_t)j * CDIM;
            float acc = 0.f;
            #pragma unroll 8
            for (int k = 0; k < 256; k++) acc = fmaf(zp[k], ep[k], acc);   // exact R1 order
            float d = fmaf(-2.f, acc, __fadd_rn(szr, g_se[j]));            // exact R1 rounding
            if (d < bd || (d == bd && j < bj)) { bd = d; bj = j; }
        }
        #pragma unroll
        for (int off = 16; off; off >>= 1) {
            float od = __shfl_down_sync(0xffffffffu, bd, off);
            int   oj = __shfl_down_sync(0xffffffffu, bj, off);
            if (od < bd || (od == bd && oj < bj)) { bd = od; bj = oj; }
        }
        if (l == 0) { out[row0 + r] = (float)bj; wsum += (double)bd; }
    }
    if (l == 0) ws[w] = wsum;
    __syncthreads();
    if (tid == 0) {
        double p = 0.0;
        #pragma unroll
        for (int i = 0; i < 16; i++) p += ws[i];
        g_partial[blockIdx.x] = p;
    }
}

// ================= loss finalize =================
__global__ void loss2_kernel(float* __restrict__ out, int out_size) {
    __shared__ double s[256];
    int t = threadIdx.x;
    s[t] = g_partial[t];
    __syncthreads();
    for (int off = 128; off; off >>= 1) {
        if (t < off) s[t] += s[t + off];
        __syncthreads();
    }
    if (t == 0 && out_size > NROW) {
        float m = (float)(s[0] / (double)((size_t)NROW * CDIM));
        out[NROW] = m + 0.25f * m;
    }
}

extern "C" void kernel_launch(void* const* d_in, const int* in_sizes, int n_in,
                              void* d_out, int out_size) {
    const float* z   = (const float*)d_in[0];   // (32,256,32,32) fp32
    const float* emb = (const float*)d_in[1];   // (1024,256)     fp32
    float* out = (float*)d_out;

    zprep_kernel<<<dim3(32, 8, 32), dim3(32, 8)>>>(z);
    eprep_kernel<<<1024, 256>>>(emb);
    se_kernel<<<1024, 64>>>(emb);

    static int smem_set = 0;
    if (!smem_set) {
        cudaFuncSetAttribute(gemm_kernel, cudaFuncAttributeMaxDynamicSharedMemorySize, SMEM_T);
        smem_set = 1;
    }
    gemm_kernel<<<256, 512, SMEM_T>>>(emb, out);   // launch #4 -> profiled slot

    loss2_kernel<<<1, 256>>>(out, out_size);
}

// round 6
// speedup vs baseline: 1.1614x; 1.1614x over previous
#include <cuda_runtime.h>
#include <cuda_bf16.h>
#include <cuda_fp16.h>
#include <math_constants.h>

#define NROW 32768
#define CDIM 256
#define NE   1024
#define MARGIN 8e-3f
#define CAP  48

// ---- static device scratch (allocation-free rule) ----
__device__ float          g_zrm[(size_t)NROW * CDIM];   // z row-major [n][c] fp32 (written by gemm)
__device__ __nv_bfloat16  g_ebf[(size_t)NE * CDIM];     // bf16(emb) [j][k]
__device__ float          g_se[NE];
__device__ int            g_cnt[NROW];
__device__ unsigned short g_cand[(size_t)NROW * CAP];
__device__ double         g_partial[4096];

// ================= PTX helpers (baseline sm_80 ISA only) =================
__device__ __forceinline__ unsigned smem_u32(const void* p) {
    unsigned a;
    asm("{ .reg .u64 t; cvta.to.shared.u64 t, %1; cvt.u32.u64 %0, t; }" : "=r"(a) : "l"(p));
    return a;
}
__device__ __forceinline__ void cp16(unsigned dst, const void* src) {
    asm volatile("cp.async.cg.shared.global [%0], [%1], 16;" :: "r"(dst), "l"(src));
}
#define CP_COMMIT() asm volatile("cp.async.commit_group;" ::: "memory")
#define CP_WAIT(n)  asm volatile("cp.async.wait_group %0;" :: "n"(n) : "memory")

__device__ __forceinline__ void ldsm4(unsigned& r0, unsigned& r1, unsigned& r2, unsigned& r3,
                                      unsigned addr) {
    asm volatile("ldmatrix.sync.aligned.m8n8.x4.shared.b16 {%0,%1,%2,%3}, [%4];"
        : "=r"(r0), "=r"(r1), "=r"(r2), "=r"(r3) : "r"(addr));
}
__device__ __forceinline__ void mma16816(float* c, const unsigned* a, unsigned b0, unsigned b1) {
    asm volatile("mma.sync.aligned.m16n8k16.row.col.f32.bf16.bf16.f32 "
        "{%0,%1,%2,%3}, {%4,%5,%6,%7}, {%8,%9}, {%0,%1,%2,%3};"
        : "+f"(c[0]), "+f"(c[1]), "+f"(c[2]), "+f"(c[3])
        : "r"(a[0]), "r"(a[1]), "r"(a[2]), "r"(a[3]), "r"(b0), "r"(b1));
}
__device__ __forceinline__ unsigned fmapu(float f) {
    unsigned b = __float_as_uint(f);
    return (b & 0x80000000u) ? ~b : (b | 0x80000000u);
}
__device__ __forceinline__ float funmapu(unsigned u) {
    return (u & 0x80000000u) ? __uint_as_float(u & 0x7fffffffu) : __uint_as_float(~u);
}

// ================= prep kernels =================
__global__ void eprep_kernel(const float* __restrict__ e) {
    int i = blockIdx.x * 256 + threadIdx.x;
    g_ebf[i] = __float2bfloat16(e[i]);
}

// per-code norms (verbatim R1 rounding — known-passing)
__global__ void se_kernel(const float* __restrict__ e) {
    int j = blockIdx.x;
    float4 v = *(const float4*)&e[j * 256 + threadIdx.x * 4];
    float s = __fadd_rn(__fadd_rn(__fmul_rn(v.x,v.x), __fmul_rn(v.y,v.y)),
                        __fadd_rn(__fmul_rn(v.z,v.z), __fmul_rn(v.w,v.w)));
    for (int off = 16; off; off >>= 1) s += __shfl_down_sync(0xffffffffu, s, off);
    __shared__ float r2[2];
    if ((threadIdx.x & 31) == 0) r2[threadIdx.x >> 5] = s;
    __syncthreads();
    if (threadIdx.x == 0) g_se[j] = __fadd_rn(r2[0], r2[1]);
}

__global__ void pinit_kernel() {   // spacer (keeps gemm in profiled slot) + deterministic init
    g_partial[blockIdx.x * 256 + threadIdx.x] = 0.0;
}

// ================= HMMA scoring + online shortlist =================
// smem: se 4KB | A 64KB | B 2x64KB (stage reuse) | min 512B | cnt 512B | lists 12KB
#define SE_OFF   0
#define A_OFF    4096
#define B_OFF    (4096 + 65536)
#define MIN_OFF  (B_OFF + 131072)          // 200704
#define CNT_OFF  (MIN_OFF + 512)
#define LIST_OFF (CNT_OFF + 512)
#define SMEM_T   (LIST_OFF + 128 * CAP * 2)  // 214016

__global__ void __launch_bounds__(512) gemm_kernel(const float* __restrict__ z) {
    extern __shared__ char sm[];
    unsigned smb = smem_u32(sm);
    const int tid = threadIdx.x, l = tid & 31, w = tid >> 5;
    const int wm = w & 3, wn = w >> 2;           // 4x4 warp grid, 32x32 tiles
    const int row0 = blockIdx.x * 128;
    float* se_sm = (float*)(sm + SE_OFF);
    unsigned* sm_min = (unsigned*)(sm + MIN_OFF);
    int* sm_cnt = (int*)(sm + CNT_OFF);
    unsigned short* sm_list = (unsigned short*)(sm + LIST_OFF);

    if (tid < 256) ((float4*)se_sm)[tid] = ((const float4*)g_se)[tid];
    if (tid < 128) { sm_min[tid] = 0xFFFFFFFFu; sm_cnt[tid] = 0; }

    // ---- phase 1: load z slice from ORIGINAL layout, transpose via staging;
    //      emit fp32 zrm tile (for rescore) + bf16 A tile (swizzled) ----
    {
        const int b = row0 >> 10, hw0 = row0 & 1023;
        float* stg = (float*)(sm + B_OFF) + w * (36 * 32);   // 4608B per warp
        #pragma unroll
        for (int tt = 0; tt < 2; tt++) {
            int ti = w * 2 + tt;            // 32 tiles: ci 0..7 (c), hi 0..3 (hw)
            int ci = ti >> 2, hi = ti & 3;
            #pragma unroll
            for (int i = 0; i < 8; i++) {
                int cl = i * 4 + (l >> 3);
                float4 v = *(const float4*)&z[((size_t)b << 18) + (size_t)(ci * 32 + cl) * 1024
                                              + hw0 + hi * 32 + (l & 7) * 4];
                *(float4*)&stg[cl * 36 + (l & 7) * 4] = v;
            }
            __syncwarp();
            int c = ci * 32 + l;
            #pragma unroll
            for (int rr = 0; rr < 32; rr++) {
                float v = stg[l * 36 + rr];
                int r = hi * 32 + rr;
                g_zrm[(size_t)(row0 + r) * 256 + c] = v;
                *(__nv_bfloat16*)(sm + A_OFF + r * 512 + ((c * 2) ^ ((r & 7) << 4))) =
                    __float2bfloat16(v);
            }
            __syncwarp();
        }
    }
    __syncthreads();   // A ready; staging region free for B

    // ---- B chunk 0 via cp.async ----
    const char* esrc = (const char*)g_ebf;
    #pragma unroll
    for (int i = 0; i < 8; i++) {
        int f = tid + i * 512, r = f >> 5, kb16 = f & 31;
        cp16(smb + B_OFF + r * 512 + ((kb16 * 16) ^ ((r & 7) << 4)),
             esrc + (size_t)r * 512 + kb16 * 16);
    }
    CP_COMMIT();

    const unsigned c16 = ((l >> 4) & 1) * 16;
    unsigned aBase[2], xA[2];
    #pragma unroll
    for (int mf = 0; mf < 2; mf++) {
        int r = wm * 32 + mf * 16 + (l & 15);
        aBase[mf] = smb + A_OFF + r * 512;
        xA[mf] = c16 ^ ((r & 7) << 4);
    }
    unsigned bRow[2], xB[2];
    #pragma unroll
    for (int nfp = 0; nfp < 2; nfp++) {
        int r = wn * 32 + nfp * 16 + ((l >> 3) & 1) * 8 + (l & 7);
        bRow[nfp] = r * 512;
        xB[nfp] = c16 ^ ((r & 7) << 4);
    }

    for (int t = 0; t < 8; t++) {
        if (t < 7) {
            const char* src = esrc + (size_t)(t + 1) * 128 * 512;
            unsigned dstb = smb + B_OFF + ((t + 1) & 1) * 65536;
            #pragma unroll
            for (int i = 0; i < 8; i++) {
                int f = tid + i * 512, r = f >> 5, kb16 = f & 31;
                cp16(dstb + r * 512 + ((kb16 * 16) ^ ((r & 7) << 4)),
                     src + (size_t)r * 512 + kb16 * 16);
            }
            CP_COMMIT();
            CP_WAIT(1);
        } else {
            CP_WAIT(0);
        }
        __syncthreads();

        float acc[2][4][4];
        #pragma unroll
        for (int mf = 0; mf < 2; mf++)
            #pragma unroll
            for (int nf = 0; nf < 4; nf++)
                #pragma unroll
                for (int q = 0; q < 4; q++) acc[mf][nf][q] = 0.f;

        unsigned bB = smb + B_OFF + (t & 1) * 65536;

        // ---- mainloop with fragment double-buffering (LDSM overlaps MMA) ----
        unsigned afr[2][2][4], bfr[2][8];
        #pragma unroll
        for (int mf = 0; mf < 2; mf++)
            ldsm4(afr[0][mf][0], afr[0][mf][1], afr[0][mf][2], afr[0][mf][3],
                  aBase[mf] + (0 ^ xA[mf]));
        #pragma unroll
        for (int nfp = 0; nfp < 2; nfp++) {
            unsigned q0, q1, q2, q3;
            ldsm4(q0, q1, q2, q3, bB + bRow[nfp] + (0 ^ xB[nfp]));
            bfr[0][nfp * 4 + 0] = q0; bfr[0][nfp * 4 + 1] = q2;
            bfr[0][nfp * 4 + 2] = q1; bfr[0][nfp * 4 + 3] = q3;
        }
        #pragma unroll
        for (int ks = 0; ks < 16; ks++) {
            const int cur = ks & 1, nxt = cur ^ 1;
            if (ks < 15) {
                #pragma unroll
                for (int mf = 0; mf < 2; mf++)
                    ldsm4(afr[nxt][mf][0], afr[nxt][mf][1], afr[nxt][mf][2], afr[nxt][mf][3],
                          aBase[mf] + (((ks + 1) << 5) ^ xA[mf]));
                #pragma unroll
                for (int nfp = 0; nfp < 2; nfp++) {
                    unsigned q0, q1, q2, q3;
                    ldsm4(q0, q1, q2, q3, bB + bRow[nfp] + (((ks + 1) << 5) ^ xB[nfp]));
                    bfr[nxt][nfp * 4 + 0] = q0; bfr[nxt][nfp * 4 + 1] = q2;
                    bfr[nxt][nfp * 4 + 2] = q1; bfr[nxt][nfp * 4 + 3] = q3;
                }
            }
            #pragma unroll
            for (int mf = 0; mf < 2; mf++)
                #pragma unroll
                for (int nf = 0; nf < 4; nf++)
                    mma16816(acc[mf][nf], afr[cur][mf], bfr[cur][nf * 2], bfr[cur][nf * 2 + 1]);
        }

        // ---- online shortlist epilogue ----
        #pragma unroll
        for (int mf = 0; mf < 2; mf++) {
            int r0l = wm * 32 + mf * 16 + (l >> 2);
            int r1l = r0l + 8;
            float mn0 = CUDART_INF_F, mn1 = CUDART_INF_F;
            #pragma unroll
            for (int nf = 0; nf < 4; nf++) {
                int gc = t * 128 + wn * 32 + nf * 8 + (l & 3) * 2;
                float se0 = se_sm[gc], se1 = se_sm[gc + 1];
                mn0 = fminf(mn0, fminf(fmaf(-2.f, acc[mf][nf][0], se0),
                                       fmaf(-2.f, acc[mf][nf][1], se1)));
                mn1 = fminf(mn1, fminf(fmaf(-2.f, acc[mf][nf][2], se0),
                                       fmaf(-2.f, acc[mf][nf][3], se1)));
            }
            mn0 = fminf(mn0, __shfl_xor_sync(0xffffffffu, mn0, 1));
            mn0 = fminf(mn0, __shfl_xor_sync(0xffffffffu, mn0, 2));
            mn1 = fminf(mn1, __shfl_xor_sync(0xffffffffu, mn1, 1));
            mn1 = fminf(mn1, __shfl_xor_sync(0xffffffffu, mn1, 2));
            if ((l & 3) == 0) {
                atomicMin(&sm_min[r0l], fmapu(mn0));
                atomicMin(&sm_min[r1l], fmapu(mn1));
            }
            __syncwarp();
            float thr0 = fminf(funmapu(((volatile unsigned*)sm_min)[r0l]), mn0) + MARGIN;
            float thr1 = fminf(funmapu(((volatile unsigned*)sm_min)[r1l]), mn1) + MARGIN;
            #pragma unroll
            for (int nf = 0; nf < 4; nf++) {
                int gc = t * 128 + wn * 32 + nf * 8 + (l & 3) * 2;
                float se0 = se_sm[gc], se1 = se_sm[gc + 1];
                float s00 = fmaf(-2.f, acc[mf][nf][0], se0);
                float s01 = fmaf(-2.f, acc[mf][nf][1], se1);
                float s10 = fmaf(-2.f, acc[mf][nf][2], se0);
                float s11 = fmaf(-2.f, acc[mf][nf][3], se1);
                if (s00 <= thr0) { int p = atomicAdd(&sm_cnt[r0l], 1); if (p < CAP) sm_list[r0l * CAP + p] = (unsigned short)gc; }
                if (s01 <= thr0) { int p = atomicAdd(&sm_cnt[r0l], 1); if (p < CAP) sm_list[r0l * CAP + p] = (unsigned short)(gc + 1); }
                if (s10 <= thr1) { int p = atomicAdd(&sm_cnt[r1l], 1); if (p < CAP) sm_list[r1l * CAP + p] = (unsigned short)gc; }
                if (s11 <= thr1) { int p = atomicAdd(&sm_cnt[r1l], 1); if (p < CAP) sm_list[r1l * CAP + p] = (unsigned short)(gc + 1); }
            }
        }
        __syncthreads();
    }

    // ---- dump shortlists ----
    if (tid < 128) g_cnt[row0 + tid] = sm_cnt[tid];
    unsigned* gl = (unsigned*)&g_cand[(size_t)row0 * CAP];
    unsigned* sl = (unsigned*)sm_list;
    #pragma unroll
    for (int k = 0; k < 6; k++) gl[tid + k * 512] = sl[tid + k * 512];
}

// ================= exact rescore (high occupancy, warp per row) =================
__global__ void __launch_bounds__(256) rescore_kernel(const float* __restrict__ emb,
                                                      float* __restrict__ out) {
    __shared__ double s_wd[8];
    int w = threadIdx.x >> 5, l = threadIdx.x & 31;
    int row = blockIdx.x * 8 + w;
    const float* zp = g_zrm + (size_t)row * CDIM;

    // per-row sz, R1-exact: 8 strided partials (mul+add), ordered combine
    int y = l & 7;
    float p = 0.f;
    #pragma unroll 8
    for (int i = 0; i < 32; i++) {
        float v = zp[y + 8 * i];
        p = __fadd_rn(p, __fmul_rn(v, v));
    }
    int base = l & 24;
    float szr = __shfl_sync(0xffffffffu, p, base);
    #pragma unroll
    for (int yy = 1; yy < 8; yy++)
        szr = __fadd_rn(szr, __shfl_sync(0xffffffffu, p, base + yy));
    szr = __shfl_sync(0xffffffffu, szr, 0);

    int cnt = g_cnt[row];
    bool ovf = (cnt > CAP);
    int n = ovf ? NE : cnt;
    float bd = CUDART_INF_F; int bj = 0x7fffffff;
    for (int i = l; i < n; i += 32) {
        int j = ovf ? i : (int)g_cand[(size_t)row * CAP + i];
        const float* ep = emb + (size_t)j * CDIM;
        float acc = 0.f;
        #pragma unroll 8
        for (int k = 0; k < 256; k++) acc = fmaf(zp[k], ep[k], acc);   // exact R1 order
        float d = fmaf(-2.f, acc, __fadd_rn(szr, g_se[j]));            // exact R1 rounding
        if (d < bd || (d == bd && j < bj)) { bd = d; bj = j; }
    }
    #pragma unroll
    for (int off = 16; off; off >>= 1) {
        float od = __shfl_down_sync(0xffffffffu, bd, off);
        int   oj = __shfl_down_sync(0xffffffffu, bj, off);
        if (od < bd || (od == bd && oj < bj)) { bd = od; bj = oj; }
    }
    if (l == 0) { out[row] = (float)bj; s_wd[w] = (double)bd; }
    __syncthreads();
    if (threadIdx.x == 0) {
        double q = 0.0;
        #pragma unroll
        for (int i = 0; i < 8; i++) q += s_wd[i];
        g_partial[blockIdx.x] = q;
    }
}

// ================= loss finalize =================
__global__ void loss2_kernel(float* __restrict__ out, int out_size) {
    __shared__ double s[1024];
    int t = threadIdx.x;
    s[t] = g_partial[t] + g_partial[t + 1024] + g_partial[t + 2048] + g_partial[t + 3072];
    __syncthreads();
    for (int off = 512; off; off >>= 1) {
        if (t < off) s[t] += s[t + off];
        __syncthreads();
    }
    if (t == 0 && out_size > NROW) {
        float m = (float)(s[0] / (double)((size_t)NROW * CDIM));
        out[NROW] = m + 0.25f * m;
    }
}

extern "C" void kernel_launch(void* const* d_in, const int* in_sizes, int n_in,
                              void* d_out, int out_size) {
    const float* z   = (const float*)d_in[0];   // (32,256,32,32) fp32
    const float* emb = (const float*)d_in[1];   // (1024,256)     fp32
    float* out = (float*)d_out;

    eprep_kernel<<<1024, 256>>>(emb);
    se_kernel<<<1024, 64>>>(emb);
    pinit_kernel<<<16, 256>>>();                 // spacer: gemm lands in profiled slot #4

    static int smem_set = 0;
    if (!smem_set) {
        cudaFuncSetAttribute(gemm_kernel, cudaFuncAttributeMaxDynamicSharedMemorySize, SMEM_T);
        smem_set = 1;
    }
    gemm_kernel<<<256, 512, SMEM_T>>>(z);

    rescore_kernel<<<4096, 256>>>(emb, out);
    loss2_kernel<<<1, 1024>>>(out, out_size);
}

// round 7
// speedup vs baseline: 1.8277x; 1.5737x over previous
#include <cuda_runtime.h>
#include <cuda_bf16.h>
#include <cuda_fp16.h>
#include <math_constants.h>

#define NROW 32768
#define CDIM 256
#define NE   1024
#define MARGIN 8e-3f
#define CAP  48

// ---- static device scratch (allocation-free rule) ----
__device__ float          g_zrm[(size_t)NROW * CDIM];   // z row-major [n][c] fp32 (written by gemm)
__device__ __nv_bfloat16  g_ebf[(size_t)NE * CDIM];     // bf16(emb) [j][k]
__device__ float          g_se[NE];
__device__ int            g_cnt[NROW];
__device__ unsigned short g_cand[(size_t)NROW * CAP];
__device__ double         g_partial[4096];

// ================= PTX helpers (baseline sm_80 ISA only) =================
__device__ __forceinline__ unsigned smem_u32(const void* p) {
    unsigned a;
    asm("{ .reg .u64 t; cvta.to.shared.u64 t, %1; cvt.u32.u64 %0, t; }" : "=r"(a) : "l"(p));
    return a;
}
__device__ __forceinline__ void cp16(unsigned dst, const void* src) {
    asm volatile("cp.async.cg.shared.global [%0], [%1], 16;" :: "r"(dst), "l"(src));
}
#define CP_COMMIT() asm volatile("cp.async.commit_group;" ::: "memory")
#define CP_WAIT(n)  asm volatile("cp.async.wait_group %0;" :: "n"(n) : "memory")

__device__ __forceinline__ void ldsm4(unsigned& r0, unsigned& r1, unsigned& r2, unsigned& r3,
                                      unsigned addr) {
    asm volatile("ldmatrix.sync.aligned.m8n8.x4.shared.b16 {%0,%1,%2,%3}, [%4];"
        : "=r"(r0), "=r"(r1), "=r"(r2), "=r"(r3) : "r"(addr));
}
__device__ __forceinline__ void mma16816(float* c, const unsigned* a, unsigned b0, unsigned b1) {
    asm volatile("mma.sync.aligned.m16n8k16.row.col.f32.bf16.bf16.f32 "
        "{%0,%1,%2,%3}, {%4,%5,%6,%7}, {%8,%9}, {%0,%1,%2,%3};"
        : "+f"(c[0]), "+f"(c[1]), "+f"(c[2]), "+f"(c[3])
        : "r"(a[0]), "r"(a[1]), "r"(a[2]), "r"(a[3]), "r"(b0), "r"(b1));
}
__device__ __forceinline__ unsigned fmapu(float f) {
    unsigned b = __float_as_uint(f);
    return (b & 0x80000000u) ? ~b : (b | 0x80000000u);
}
__device__ __forceinline__ float funmapu(unsigned u) {
    return (u & 0x80000000u) ? __uint_as_float(u & 0x7fffffffu) : __uint_as_float(~u);
}

// ================= prep kernels =================
__global__ void eprep_kernel(const float* __restrict__ e) {
    int i = blockIdx.x * 256 + threadIdx.x;
    g_ebf[i] = __float2bfloat16(e[i]);
}

// per-code norms (verbatim R1 rounding — known-passing)
__global__ void se_kernel(const float* __restrict__ e) {
    int j = blockIdx.x;
    float4 v = *(const float4*)&e[j * 256 + threadIdx.x * 4];
    float s = __fadd_rn(__fadd_rn(__fmul_rn(v.x,v.x), __fmul_rn(v.y,v.y)),
                        __fadd_rn(__fmul_rn(v.z,v.z), __fmul_rn(v.w,v.w)));
    for (int off = 16; off; off >>= 1) s += __shfl_down_sync(0xffffffffu, s, off);
    __shared__ float r2[2];
    if ((threadIdx.x & 31) == 0) r2[threadIdx.x >> 5] = s;
    __syncthreads();
    if (threadIdx.x == 0) g_se[j] = __fadd_rn(r2[0], r2[1]);
}

__global__ void pinit_kernel() {   // spacer (keeps gemm in profiled slot) + deterministic init
    g_partial[blockIdx.x * 256 + threadIdx.x] = 0.0;
}

// ================= HMMA scoring: pass A (final min) + pass B (tight shortlist) =================
// smem: se 4KB | A 64KB | B 2x64KB (stage reuse) | min 512B | thr 512B | cnt 512B | lists 12KB
#define SE_OFF   0
#define A_OFF    4096
#define B_OFF    (4096 + 65536)
#define MIN_OFF  (B_OFF + 131072)          // 200704
#define THR_OFF  (MIN_OFF + 512)
#define CNT_OFF  (THR_OFF + 512)
#define LIST_OFF (CNT_OFF + 512)
#define SMEM_T   (LIST_OFF + 128 * CAP * 2)  // 214528

__global__ void __launch_bounds__(512) gemm_kernel(const float* __restrict__ z) {
    extern __shared__ char sm[];
    unsigned smb = smem_u32(sm);
    const int tid = threadIdx.x, l = tid & 31, w = tid >> 5;
    const int wm = w & 3, wn = w >> 2;           // 4x4 warp grid, 32x32 tiles
    const int row0 = blockIdx.x * 128;
    float* se_sm = (float*)(sm + SE_OFF);
    unsigned* sm_min = (unsigned*)(sm + MIN_OFF);
    float* sm_thr = (float*)(sm + THR_OFF);
    int* sm_cnt = (int*)(sm + CNT_OFF);
    unsigned short* sm_list = (unsigned short*)(sm + LIST_OFF);

    if (tid < 256) ((float4*)se_sm)[tid] = ((const float4*)g_se)[tid];
    if (tid < 128) { sm_min[tid] = 0xFFFFFFFFu; sm_cnt[tid] = 0; }

    // ---- phase 1: load z slice from ORIGINAL layout, transpose via staging;
    //      emit fp32 zrm tile (for rescore) + bf16 A tile (swizzled) ----
    {
        const int b = row0 >> 10, hw0 = row0 & 1023;
        float* stg = (float*)(sm + B_OFF) + w * (36 * 32);   // 4608B per warp
        #pragma unroll
        for (int tt = 0; tt < 2; tt++) {
            int ti = w * 2 + tt;            // 32 tiles: ci 0..7 (c), hi 0..3 (hw)
            int ci = ti >> 2, hi = ti & 3;
            #pragma unroll
            for (int i = 0; i < 8; i++) {
                int cl = i * 4 + (l >> 3);
                float4 v = *(const float4*)&z[((size_t)b << 18) + (size_t)(ci * 32 + cl) * 1024
                                              + hw0 + hi * 32 + (l & 7) * 4];
                *(float4*)&stg[cl * 36 + (l & 7) * 4] = v;
            }
            __syncwarp();
            int c = ci * 32 + l;
            #pragma unroll
            for (int rr = 0; rr < 32; rr++) {
                float v = stg[l * 36 + rr];
                int r = hi * 32 + rr;
                g_zrm[(size_t)(row0 + r) * 256 + c] = v;
                *(__nv_bfloat16*)(sm + A_OFF + r * 512 + ((c * 2) ^ ((r & 7) << 4))) =
                    __float2bfloat16(v);
            }
            __syncwarp();
        }
    }
    __syncthreads();   // A ready; staging region free for B

    const unsigned c16 = ((l >> 4) & 1) * 16;
    unsigned aBase[2], xA[2];
    #pragma unroll
    for (int mf = 0; mf < 2; mf++) {
        int r = wm * 32 + mf * 16 + (l & 15);
        aBase[mf] = smb + A_OFF + r * 512;
        xA[mf] = c16 ^ ((r & 7) << 4);
    }
    unsigned bRow[2], xB[2];
    #pragma unroll
    for (int nfp = 0; nfp < 2; nfp++) {
        int r = wn * 32 + nfp * 16 + ((l >> 3) & 1) * 8 + (l & 7);
        bRow[nfp] = r * 512;
        xB[nfp] = c16 ^ ((r & 7) << 4);
    }
    const char* esrc = (const char*)g_ebf;

    for (int pass = 0; pass < 2; pass++) {
        // ---- B chunk 0 via cp.async (pass B re-streams from L2-resident codebook) ----
        #pragma unroll
        for (int i = 0; i < 8; i++) {
            int f = tid + i * 512, r = f >> 5, kb16 = f & 31;
            cp16(smb + B_OFF + r * 512 + ((kb16 * 16) ^ ((r & 7) << 4)),
                 esrc + (size_t)r * 512 + kb16 * 16);
        }
        CP_COMMIT();

        for (int t = 0; t < 8; t++) {
            if (t < 7) {
                const char* src = esrc + (size_t)(t + 1) * 128 * 512;
                unsigned dstb = smb + B_OFF + ((t + 1) & 1) * 65536;
                #pragma unroll
                for (int i = 0; i < 8; i++) {
                    int f = tid + i * 512, r = f >> 5, kb16 = f & 31;
                    cp16(dstb + r * 512 + ((kb16 * 16) ^ ((r & 7) << 4)),
                         src + (size_t)r * 512 + kb16 * 16);
                }
                CP_COMMIT();
                CP_WAIT(1);
            } else {
                CP_WAIT(0);
            }
            __syncthreads();

            float acc[2][4][4];
            #pragma unroll
            for (int mf = 0; mf < 2; mf++)
                #pragma unroll
                for (int nf = 0; nf < 4; nf++)
                    #pragma unroll
                    for (int q = 0; q < 4; q++) acc[mf][nf][q] = 0.f;

            unsigned bB = smb + B_OFF + (t & 1) * 65536;

            // ---- mainloop with fragment double-buffering (LDSM overlaps MMA) ----
            unsigned afr[2][2][4], bfr[2][8];
            #pragma unroll
            for (int mf = 0; mf < 2; mf++)
                ldsm4(afr[0][mf][0], afr[0][mf][1], afr[0][mf][2], afr[0][mf][3],
                      aBase[mf] + (0 ^ xA[mf]));
            #pragma unroll
            for (int nfp = 0; nfp < 2; nfp++) {
                unsigned q0, q1, q2, q3;
                ldsm4(q0, q1, q2, q3, bB + bRow[nfp] + (0 ^ xB[nfp]));
                bfr[0][nfp * 4 + 0] = q0; bfr[0][nfp * 4 + 1] = q2;
                bfr[0][nfp * 4 + 2] = q1; bfr[0][nfp * 4 + 3] = q3;
            }
            #pragma unroll
            for (int ks = 0; ks < 16; ks++) {
                const int cur = ks & 1, nxt = cur ^ 1;
                if (ks < 15) {
                    #pragma unroll
                    for (int mf = 0; mf < 2; mf++)
                        ldsm4(afr[nxt][mf][0], afr[nxt][mf][1], afr[nxt][mf][2], afr[nxt][mf][3],
                              aBase[mf] + (((ks + 1) << 5) ^ xA[mf]));
                    #pragma unroll
                    for (int nfp = 0; nfp < 2; nfp++) {
                        unsigned q0, q1, q2, q3;
                        ldsm4(q0, q1, q2, q3, bB + bRow[nfp] + (((ks + 1) << 5) ^ xB[nfp]));
                        bfr[nxt][nfp * 4 + 0] = q0; bfr[nxt][nfp * 4 + 1] = q2;
                        bfr[nxt][nfp * 4 + 2] = q1; bfr[nxt][nfp * 4 + 3] = q3;
                    }
                }
                #pragma unroll
                for (int mf = 0; mf < 2; mf++)
                    #pragma unroll
                    for (int nf = 0; nf < 4; nf++)
                        mma16816(acc[mf][nf], afr[cur][mf], bfr[cur][nf * 2], bfr[cur][nf * 2 + 1]);
            }

            if (pass == 0) {
                // ---- pass A epilogue: per-row running min only ----
                #pragma unroll
                for (int mf = 0; mf < 2; mf++) {
                    int r0l = wm * 32 + mf * 16 + (l >> 2);
                    int r1l = r0l + 8;
                    float mn0 = CUDART_INF_F, mn1 = CUDART_INF_F;
                    #pragma unroll
                    for (int nf = 0; nf < 4; nf++) {
                        int gc = t * 128 + wn * 32 + nf * 8 + (l & 3) * 2;
                        float se0 = se_sm[gc], se1 = se_sm[gc + 1];
                        mn0 = fminf(mn0, fminf(fmaf(-2.f, acc[mf][nf][0], se0),
                                               fmaf(-2.f, acc[mf][nf][1], se1)));
                        mn1 = fminf(mn1, fminf(fmaf(-2.f, acc[mf][nf][2], se0),
                                               fmaf(-2.f, acc[mf][nf][3], se1)));
                    }
                    mn0 = fminf(mn0, __shfl_xor_sync(0xffffffffu, mn0, 1));
                    mn0 = fminf(mn0, __shfl_xor_sync(0xffffffffu, mn0, 2));
                    mn1 = fminf(mn1, __shfl_xor_sync(0xffffffffu, mn1, 1));
                    mn1 = fminf(mn1, __shfl_xor_sync(0xffffffffu, mn1, 2));
                    if ((l & 3) == 0) {
                        atomicMin(&sm_min[r0l], fmapu(mn0));
                        atomicMin(&sm_min[r1l], fmapu(mn1));
                    }
                }
            } else {
                // ---- pass B epilogue: push candidates against FINAL threshold ----
                #pragma unroll
                for (int mf = 0; mf < 2; mf++) {
                    int r0l = wm * 32 + mf * 16 + (l >> 2);
                    int r1l = r0l + 8;
                    float thr0 = sm_thr[r0l], thr1 = sm_thr[r1l];
                    #pragma unroll
                    for (int nf = 0; nf < 4; nf++) {
                        int gc = t * 128 + wn * 32 + nf * 8 + (l & 3) * 2;
                        float se0 = se_sm[gc], se1 = se_sm[gc + 1];
                        float s00 = fmaf(-2.f, acc[mf][nf][0], se0);
                        float s01 = fmaf(-2.f, acc[mf][nf][1], se1);
                        float s10 = fmaf(-2.f, acc[mf][nf][2], se0);
                        float s11 = fmaf(-2.f, acc[mf][nf][3], se1);
                        if (s00 <= thr0) { int p = atomicAdd(&sm_cnt[r0l], 1); if (p < CAP) sm_list[r0l * CAP + p] = (unsigned short)gc; }
                        if (s01 <= thr0) { int p = atomicAdd(&sm_cnt[r0l], 1); if (p < CAP) sm_list[r0l * CAP + p] = (unsigned short)(gc + 1); }
                        if (s10 <= thr1) { int p = atomicAdd(&sm_cnt[r1l], 1); if (p < CAP) sm_list[r1l * CAP + p] = (unsigned short)gc; }
                        if (s11 <= thr1) { int p = atomicAdd(&sm_cnt[r1l], 1); if (p < CAP) sm_list[r1l * CAP + p] = (unsigned short)(gc + 1); }
                    }
                }
            }
            __syncthreads();
        }
        if (pass == 0) {
            if (tid < 128) sm_thr[tid] = funmapu(sm_min[tid]) + MARGIN;
            __syncthreads();
        }
    }

    // ---- dump shortlists ----
    if (tid < 128) g_cnt[row0 + tid] = sm_cnt[tid];
    unsigned* gl = (unsigned*)&g_cand[(size_t)row0 * CAP];
    unsigned* sl = (unsigned*)sm_list;
    #pragma unroll
    for (int k = 0; k < 6; k++) gl[tid + k * 512] = sl[tid + k * 512];
}

// ================= exact rescore (high occupancy, warp per row) =================
__global__ void __launch_bounds__(256) rescore_kernel(const float* __restrict__ emb,
                                                      float* __restrict__ out) {
    __shared__ double s_wd[8];
    int w = threadIdx.x >> 5, l = threadIdx.x & 31;
    int row = blockIdx.x * 8 + w;
    const float* zp = g_zrm + (size_t)row * CDIM;

    // per-row sz, R1-exact: 8 strided partials (mul+add), ordered combine
    int y = l & 7;
    float p = 0.f;
    #pragma unroll 8
    for (int i = 0; i < 32; i++) {
        float v = zp[y + 8 * i];
        p = __fadd_rn(p, __fmul_rn(v, v));
    }
    int base = l & 24;
    float szr = __shfl_sync(0xffffffffu, p, base);
    #pragma unroll
    for (int yy = 1; yy < 8; yy++)
        szr = __fadd_rn(szr, __shfl_sync(0xffffffffu, p, base + yy));
    szr = __shfl_sync(0xffffffffu, szr, 0);

    int cnt = g_cnt[row];
    bool ovf = (cnt > CAP);
    int n = ovf ? NE : cnt;
    float bd = CUDART_INF_F; int bj = 0x7fffffff;
    for (int i = l; i < n; i += 32) {
        int j = ovf ? i : (int)g_cand[(size_t)row * CAP + i];
        const float* ep = emb + (size_t)j * CDIM;
        float acc = 0.f;
        #pragma unroll 8
        for (int k = 0; k < 256; k++) acc = fmaf(zp[k], ep[k], acc);   // exact R1 order
        float d = fmaf(-2.f, acc, __fadd_rn(szr, g_se[j]));            // exact R1 rounding
        if (d < bd || (d == bd && j < bj)) { bd = d; bj = j; }
    }
    #pragma unroll
    for (int off = 16; off; off >>= 1) {
        float od = __shfl_down_sync(0xffffffffu, bd, off);
        int   oj = __shfl_down_sync(0xffffffffu, bj, off);
        if (od < bd || (od == bd && oj < bj)) { bd = od; bj = oj; }
    }
    if (l == 0) { out[row] = (float)bj; s_wd[w] = (double)bd; }
    __syncthreads();
    if (threadIdx.x == 0) {
        double q = 0.0;
        #pragma unroll
        for (int i = 0; i < 8; i++) q += s_wd[i];
        g_partial[blockIdx.x] = q;
    }
}

// ================= loss finalize =================
__global__ void loss2_kernel(float* __restrict__ out, int out_size) {
    __shared__ double s[1024];
    int t = threadIdx.x;
    s[t] = g_partial[t] + g_partial[t + 1024] + g_partial[t + 2048] + g_partial[t + 3072];
    __syncthreads();
    for (int off = 512; off; off >>= 1) {
        if (t < off) s[t] += s[t + off];
        __syncthreads();
    }
    if (t == 0 && out_size > NROW) {
        float m = (float)(s[0] / (double)((size_t)NROW * CDIM));
        out[NROW] = m + 0.25f * m;
    }
}

extern "C" void kernel_launch(void* const* d_in, const int* in_sizes, int n_in,
                              void* d_out, int out_size) {
    const float* z   = (const float*)d_in[0];   // (32,256,32,32) fp32
    const float* emb = (const float*)d_in[1];   // (1024,256)     fp32
    float* out = (float*)d_out;

    eprep_kernel<<<1024, 256>>>(emb);
    se_kernel<<<1024, 64>>>(emb);
    pinit_kernel<<<16, 256>>>();                 // spacer: gemm lands in profiled slot #4

    static int smem_set = 0;
    if (!smem_set) {
        cudaFuncSetAttribute(gemm_kernel, cudaFuncAttributeMaxDynamicSharedMemorySize, SMEM_T);
        smem_set = 1;
    }
    gemm_kernel<<<256, 512, SMEM_T>>>(z);

    rescore_kernel<<<4096, 256>>>(emb, out);
    loss2_kernel<<<1, 1024>>>(out, out_size);
}